// round 15
// baseline (speedup 1.0000x reference)
#include <cuda_runtime.h>
#include <cuda_bf16.h>
#include <mma.h>
#include <cstdint>

using namespace nvcuda;

#define N_EMBD        256
#define N_INPUTS      66
#define N_LEVELS      8
#define AND_PER_LEVEL 4096
#define NOT_PER_LEVEL 2048
#define LEVEL_N       (AND_PER_LEVEL + NOT_PER_LEVEL)
#define N_HIDDEN      1024
#define N_HID_LAYERS  8
#define LN_EPS        1e-5f

// ---------------------------------------------------------------------------
// Scratch: static device globals. Weights kept [K, N] row-major (as given).
// ---------------------------------------------------------------------------
__device__ __align__(256) __nv_bfloat16 g_win_hi [(size_t)512 * 1024];
__device__ __align__(256) __nv_bfloat16 g_win_lo [(size_t)512 * 1024];
__device__ __align__(256) __nv_bfloat16 g_whid_hi[(size_t)8 * 1024 * 1024];
__device__ __align__(256) __nv_bfloat16 g_whid_lo[(size_t)8 * 1024 * 1024];
__device__ __align__(256) __nv_bfloat16 g_wout_hi[(size_t)1024 * 256];
__device__ __align__(256) __nv_bfloat16 g_wout_lo[(size_t)1024 * 256];
__device__ __align__(256) __nv_bfloat16 g_act0_hi[(size_t)4096 * 1024];
__device__ __align__(256) __nv_bfloat16 g_act0_lo[(size_t)4096 * 1024];
__device__ __align__(256) __nv_bfloat16 g_act1_hi[(size_t)4096 * 1024];
__device__ __align__(256) __nv_bfloat16 g_act1_lo[(size_t)4096 * 1024];

// ---------------------------------------------------------------------------
__device__ __forceinline__ void split2(float v, __nv_bfloat16& hi, __nv_bfloat16& lo) {
    hi = __float2bfloat16(v);
    lo = __float2bfloat16(v - __bfloat162float(hi));
}

__device__ __forceinline__ uint32_t smem_u32(const void* p) {
    uint32_t a;
    asm("{ .reg .u64 t; cvta.to.shared.u64 t, %1; cvt.u32.u64 %0, t; }" : "=r"(a) : "l"(p));
    return a;
}

#define CP_ASYNC16(dst, src) \
    asm volatile("cp.async.cg.shared.global [%0], [%1], 16;" :: "r"(dst), "l"(src) : "memory")
#define CP_COMMIT() asm volatile("cp.async.commit_group;" ::: "memory")
#define CP_WAIT1()  asm volatile("cp.async.wait_group 1;" ::: "memory")
#define CP_WAIT0()  asm volatile("cp.async.wait_group 0;" ::: "memory")

// ---------------------------------------------------------------------------
// Elementwise kernels
// ---------------------------------------------------------------------------
// dst_sel: 0 -> W_in, 1 -> W_hid, 2 -> W_out
__global__ void split_kernel(const float* __restrict__ src, int dst_sel, int n) {
    int i = blockIdx.x * blockDim.x + threadIdx.x;
    if (i >= n) return;
    __nv_bfloat16 h, l;
    split2(src[i], h, l);
    __nv_bfloat16 *hi, *lo;
    if (dst_sel == 0)      { hi = g_win_hi;  lo = g_win_lo;  }
    else if (dst_sel == 1) { hi = g_whid_hi; lo = g_whid_lo; }
    else                   { hi = g_wout_hi; lo = g_wout_lo; }
    hi[i] = h; lo[i] = l;
}

__global__ void init_kernel(const float* __restrict__ embd, float* __restrict__ out) {
    int i = blockIdx.x * blockDim.x + threadIdx.x;
    if (i < N_INPUTS * N_EMBD) out[i] = embd[i];
}

// Fused: gather (build h = [embd[xa], embd[ya]] into act0, 4096x512 hi/lo)
// and NOT scatter (rows [s+4096, s+6144) = -embd[xn]); both only read rows < s,
// and their writes are disjoint, so one kernel is safe.
#define GATHER_WORK (AND_PER_LEVEL * 512)
#define NOT_WORK    (NOT_PER_LEVEL * N_EMBD)
__global__ void gather_not_kernel(float* __restrict__ node,
                                  const int* __restrict__ xe, const int* __restrict__ ye,
                                  int s) {
    int i = blockIdx.x * blockDim.x + threadIdx.x;
    if (i < GATHER_WORK) {
        int m = i >> 9, c = i & 511;
        int src = (c < 256) ? xe[s + m] : ye[s + m];
        float v = node[(size_t)src * N_EMBD + (c & 255)];
        __nv_bfloat16 h, l; split2(v, h, l);
        g_act0_hi[i] = h; g_act0_lo[i] = l;
    } else if (i < GATHER_WORK + NOT_WORK) {
        int j = i - GATHER_WORK;
        int r = j >> 8, c = j & 255;
        int src = xe[s + AND_PER_LEVEL + r];
        node[(size_t)(s + AND_PER_LEVEL + r) * N_EMBD + c] = -node[(size_t)src * N_EMBD + c];
    }
}

// ---------------------------------------------------------------------------
// Split-bf16 pipelined GEMM, 128 threads / 4 warps.
// C = (Ahi+Alo) @ (Bhi+Blo) dropping lo*lo. Block tile BM x BN, K-chunk 32.
// Warp tile (BM/WROWS) x 64. Inner loop is phase-ordered for long RAW gaps:
//   phase1: 16x hi*hi (acc reuse distance 16)
//   phase2: 16x lo*hi (distance 16)
//   phase3: hi*lo with B-lo streamed per-n (distance >= 12)
// Peak live regs ~ acc(128) + A frags(64) + B frags(32+8) < 255 -> no spills.
// 3-stage cp.async pipeline. Hidden config (128x128) fits 2 CTAs/SM.
// fuse=1: relu(x+bias) -> bf16 hi/lo into act[out_sel] (row stride Nout).
// fuse=2: bias + LayerNorm over full 256-col rows -> f32 outp rows [s+rowBase..].
// ---------------------------------------------------------------------------
#define A_LD 40

template<int BM, int BN>
__global__ __launch_bounds__(128, 2) void gemm_pipe(
    int K, int Nout, int a_sel, int b_sel, int layer, int out_sel, int fuse,
    const float* __restrict__ bias, float* __restrict__ outp, int s,
    const float* __restrict__ ln_g, const float* __restrict__ ln_b) {

    constexpr int WCOLS = BN / 64;
    constexpr int WROWS = 4 / WCOLS;
    constexpr int WM    = BM / WROWS;       // warp tile M (64 both configs)
    constexpr int MF    = WM / 16;          // 4
    constexpr int NF    = 4;                // warp tile N = 64
    constexpr int B_LD  = BN + 8;
    constexpr uint32_t ASB = 2u * BM * A_LD * 2u;
    constexpr uint32_t BSB = 2u * 32 * B_LD * 2u;
    constexpr uint32_t SS  = ASB + BSB;

    extern __shared__ __align__(128) char dsm[];

    const int tid = threadIdx.x, warpId = tid >> 5, lane = tid & 31;
    const int wm = warpId / WCOLS, wn = warpId % WCOLS;
    const int rowBase = blockIdx.y * BM;
    const int colBase = blockIdx.x * BN;

    const __nv_bfloat16* Ahi = a_sel ? g_act1_hi : g_act0_hi;
    const __nv_bfloat16* Alo = a_sel ? g_act1_lo : g_act0_lo;
    const __nv_bfloat16 *Bhi, *Blo;
    if (b_sel == 0)      { Bhi = g_win_hi;  Blo = g_win_lo; }
    else if (b_sel == 1) { Bhi = g_whid_hi + (size_t)layer * N_HIDDEN * N_HIDDEN;
                           Blo = g_whid_lo + (size_t)layer * N_HIDDEN * N_HIDDEN; }
    else                 { Bhi = g_wout_hi; Blo = g_wout_lo; }

    const uint32_t sbase0 = smem_u32(dsm);

    wmma::fragment<wmma::accumulator, 16, 16, 16, float> acc[MF][NF];
#pragma unroll
    for (int m = 0; m < MF; m++)
#pragma unroll
        for (int n = 0; n < NF; n++)
            wmma::fill_fragment(acc[m][n], 0.0f);

    const int NK = K >> 5;   // 32-K chunks

    auto load_stage = [&](int stg, int k0) {
        const uint32_t sb = sbase0 + (uint32_t)stg * SS;
        // A hi/lo: BM x 32 bf16 = BM*4 16B vectors each half
#pragma unroll
        for (int h = 0; h < 2; h++) {
            const __nv_bfloat16* ap = h ? Alo : Ahi;
            const uint32_t so = sb + h * (BM * A_LD * 2u);
#pragma unroll
            for (int i = 0; i < (BM * 4) / 128; i++) {
                int v = tid + i * 128;
                int r = v >> 2, cv = v & 3;
                CP_ASYNC16(so + (uint32_t)(r * A_LD + cv * 8) * 2u,
                           ap + (size_t)(rowBase + r) * K + k0 + cv * 8);
            }
        }
        // B hi/lo: 32 x BN bf16 = 4*BN 16B vectors each half
#pragma unroll
        for (int h = 0; h < 2; h++) {
            const __nv_bfloat16* bp = h ? Blo : Bhi;
            const uint32_t so = sb + ASB + h * (32 * B_LD * 2u);
#pragma unroll
            for (int i = 0; i < (4 * BN) / 128; i++) {
                int v = tid + i * 128;
                int r = v / (BN / 8), cv = v % (BN / 8);
                CP_ASYNC16(so + (uint32_t)(r * B_LD + cv * 8) * 2u,
                           bp + (size_t)(k0 + r) * Nout + colBase + cv * 8);
            }
        }
        CP_COMMIT();
    };

    // prologue: stages 0, 1
    load_stage(0, 0);
    load_stage(1, 32);

    for (int kt = 0; kt < NK; kt++) {
        if (kt + 1 < NK) CP_WAIT1(); else CP_WAIT0();
        __syncthreads();
        if (kt + 2 < NK) load_stage((kt + 2) % 3, (kt + 2) * 32);

        const int stg = kt % 3;
        __nv_bfloat16* sA   = (__nv_bfloat16*)(dsm + (size_t)stg * SS);
        __nv_bfloat16* sAlo = sA + BM * A_LD;
        __nv_bfloat16* sB   = (__nv_bfloat16*)(dsm + (size_t)stg * SS + ASB);
        __nv_bfloat16* sBlo = sB + 32 * B_LD;

#pragma unroll
        for (int ks = 0; ks < 32; ks += 16) {
            // Phase 1: hi*hi — load fah + fbh, 16 MMAs, each acc touched once.
            wmma::fragment<wmma::matrix_a, 16, 16, 16, __nv_bfloat16, wmma::row_major> fah[MF];
            wmma::fragment<wmma::matrix_b, 16, 16, 16, __nv_bfloat16, wmma::row_major> fbh[NF];
#pragma unroll
            for (int m = 0; m < MF; m++)
                wmma::load_matrix_sync(fah[m], sA + (wm * WM + m * 16) * A_LD + ks, A_LD);
#pragma unroll
            for (int n = 0; n < NF; n++)
                wmma::load_matrix_sync(fbh[n], sB + ks * B_LD + wn * 64 + n * 16, B_LD);
#pragma unroll
            for (int m = 0; m < MF; m++)
#pragma unroll
                for (int n = 0; n < NF; n++)
                    wmma::mma_sync(acc[m][n], fah[m], fbh[n], acc[m][n]);

            // Phase 2: lo*hi — load fal, 16 MMAs (reuse distance 16).
            {
                wmma::fragment<wmma::matrix_a, 16, 16, 16, __nv_bfloat16, wmma::row_major> fal[MF];
#pragma unroll
                for (int m = 0; m < MF; m++)
                    wmma::load_matrix_sync(fal[m], sAlo + (wm * WM + m * 16) * A_LD + ks, A_LD);
#pragma unroll
                for (int m = 0; m < MF; m++)
#pragma unroll
                    for (int n = 0; n < NF; n++)
                        wmma::mma_sync(acc[m][n], fal[m], fbh[n], acc[m][n]);
            }

            // Phase 3: hi*lo — stream one B-lo fragment per n (distance >= 12).
#pragma unroll
            for (int n = 0; n < NF; n++) {
                wmma::fragment<wmma::matrix_b, 16, 16, 16, __nv_bfloat16, wmma::row_major> fbl;
                wmma::load_matrix_sync(fbl, sBlo + ks * B_LD + wn * 64 + n * 16, B_LD);
#pragma unroll
                for (int m = 0; m < MF; m++)
                    wmma::mma_sync(acc[m][n], fah[m], fbl, acc[m][n]);
            }
        }
    }

    __syncthreads();   // pipeline smem reads done; safe to reuse smem below

    if (fuse == 1) {
        __nv_bfloat16* Ohi = out_sel ? g_act1_hi : g_act0_hi;
        __nv_bfloat16* Olo = out_sel ? g_act1_lo : g_act0_lo;
        float* epiw = (float*)dsm + warpId * (WM * 16);
#pragma unroll
        for (int n = 0; n < NF; n++) {
#pragma unroll
            for (int m = 0; m < MF; m++)
                wmma::store_matrix_sync(epiw + m * 256, acc[m][n], 16, wmma::mem_row_major);
            __syncwarp();
            const int gc0 = colBase + wn * 64 + n * 16;
#pragma unroll
            for (int ii = 0; ii < WM / 2; ii++) {
                int i = lane + ii * 32;
                int r = i >> 4, c = i & 15;
                float v = fmaxf(epiw[i] + __ldg(bias + gc0 + c), 0.0f);
                __nv_bfloat16 h, l; split2(v, h, l);
                size_t gi = (size_t)(rowBase + wm * WM + r) * Nout + gc0 + c;
                Ohi[gi] = h; Olo[gi] = l;
            }
            __syncwarp();
        }
    } else {
        // fuse == 2: bias + LayerNorm (BN == 256, colBase == 0)
        float* cbuf = (float*)dsm;                       // [BM][260]
#pragma unroll
        for (int m = 0; m < MF; m++)
#pragma unroll
            for (int n = 0; n < NF; n++)
                wmma::store_matrix_sync(cbuf + (wm * WM + m * 16) * 260 + wn * 64 + n * 16,
                                        acc[m][n], 260, wmma::mem_row_major);
        __syncthreads();
        const int rpw = BM / 4;
        for (int j = 0; j < rpw; j++) {
            int r = warpId * rpw + j;
            const float* row = cbuf + r * 260;
            float vals[8];
            float sum = 0.f, sq = 0.f;
#pragma unroll
            for (int k = 0; k < 8; k++) {
                int c = lane + k * 32;
                float v = row[c] + __ldg(bias + c);
                vals[k] = v; sum += v; sq += v * v;
            }
#pragma unroll
            for (int o = 16; o > 0; o >>= 1) {
                sum += __shfl_xor_sync(0xFFFFFFFFu, sum, o);
                sq  += __shfl_xor_sync(0xFFFFFFFFu, sq,  o);
            }
            float mu  = sum * (1.0f / N_EMBD);
            float var = sq * (1.0f / N_EMBD) - mu * mu;
            float inv = rsqrtf(var + LN_EPS);
            float* orow = outp + (size_t)(s + rowBase + r) * N_EMBD;
#pragma unroll
            for (int k = 0; k < 8; k++) {
                int c = lane + k * 32;
                orow[c] = (vals[k] - mu) * inv * __ldg(ln_g + c) + __ldg(ln_b + c);
            }
        }
    }
}

// ---------------------------------------------------------------------------
// Launch: kernel launches only; graph-capturable; no allocation; no sync.
// Order keeps the first GEMM at launch index 3 (ncu capture slot).
// ---------------------------------------------------------------------------
extern "C" void kernel_launch(void* const* d_in, const int* in_sizes, int n_in,
                              void* d_out, int out_size) {
    (void)in_sizes; (void)n_in; (void)out_size;

    const int*   xe         = (const int*)d_in[1];
    const int*   ye         = (const int*)d_in[2];
    const float* input_embd = (const float*)d_in[3];
    const float* W_in       = (const float*)d_in[4];
    const float* b_in       = (const float*)d_in[5];
    const float* W_hid      = (const float*)d_in[6];
    const float* b_hid      = (const float*)d_in[7];
    const float* W_out      = (const float*)d_in[8];
    const float* b_out      = (const float*)d_in[9];
    const float* ln_g       = (const float*)d_in[10];
    const float* ln_b       = (const float*)d_in[11];
    float*       out        = (float*)d_out;

    // Stage sizes (bytes): must match device constexprs
    const uint32_t SS_H = (2u * 128 * A_LD * 2u) + (2u * 32 * 136 * 2u);  // 37888 (BM=128,BN=128)
    const uint32_t SS_O = (2u * 64  * A_LD * 2u) + (2u * 32 * 264 * 2u);  // 44032 (BM=64, BN=256)
    cudaFuncSetAttribute((const void*)gemm_pipe<128, 128>,
                         cudaFuncAttributeMaxDynamicSharedMemorySize, 3 * SS_H);
    cudaFuncSetAttribute((const void*)gemm_pipe<64, 256>,
                         cudaFuncAttributeMaxDynamicSharedMemorySize, 3 * SS_O);

    const dim3 gridH(N_HIDDEN / 128, AND_PER_LEVEL / 128);  // (8, 32) = 256 CTAs
    const dim3 gridO(1, AND_PER_LEVEL / 64);                // (1, 64) = 64 CTAs
    const int  gnBlocks = (GATHER_WORK + NOT_WORK + 255) / 256;

    // --- prologue arranged so launch #3 is a GEMM (ncu capture target) ---
    split_kernel<<<(512 * 1024 + 255) / 256, 256>>>(W_in, 0, 512 * 1024);          // 0
    init_kernel<<<(N_INPUTS * N_EMBD + 255) / 256, 256>>>(input_embd, out);        // 1
    {
        const int s0 = N_INPUTS;
        gather_not_kernel<<<gnBlocks, 256>>>(out, xe, ye, s0);                     // 2
        gemm_pipe<128, 128><<<gridH, 128, 3 * SS_H>>>(512, N_HIDDEN, 0, 0, 0, 1, 1,
                                                      b_in, nullptr, 0, nullptr, nullptr); // 3
    }
    split_kernel<<<(8 * 1024 * 1024 + 255) / 256, 256>>>(W_hid, 1, 8 * 1024 * 1024); // 4
    split_kernel<<<(1024 * 256 + 255) / 256, 256>>>(W_out, 2, 1024 * 256);           // 5

    for (int l = 0; l < N_LEVELS; l++) {
        const int s = N_INPUTS + l * LEVEL_N;

        if (l > 0) {
            gather_not_kernel<<<gnBlocks, 256>>>(out, xe, ye, s);
            // input layer: act0 (4096x512) @ W_in (512x1024) -> act1 (relu, split)
            gemm_pipe<128, 128><<<gridH, 128, 3 * SS_H>>>(512, N_HIDDEN, 0, 0, 0, 1, 1,
                                                          b_in, nullptr, 0, nullptr, nullptr);
        }

        // hidden layers: ping-pong act1 <-> act0
        for (int i = 0; i < N_HID_LAYERS; i++) {
            int a_sel = (i & 1) ? 0 : 1;
            int o_sel = 1 - a_sel;
            gemm_pipe<128, 128><<<gridH, 128, 3 * SS_H>>>(N_HIDDEN, N_HIDDEN, a_sel, 1, i, o_sel, 1,
                                                          b_hid + (size_t)i * N_HIDDEN,
                                                          nullptr, 0, nullptr, nullptr);
        }

        // output layer: act1 (4096x1024) @ W_out (1024x256) -> bias+LN -> out
        gemm_pipe<64, 256><<<gridO, 128, 3 * SS_O>>>(N_HIDDEN, N_EMBD, 1, 2, 0, 0, 2,
                                                     b_out, out, s, ln_g, ln_b);
    }
}

// round 16
// speedup vs baseline: 1.2212x; 1.2212x over previous
#include <cuda_runtime.h>
#include <cuda_bf16.h>
#include <cstdint>

#define N_EMBD        256
#define N_INPUTS      66
#define N_LEVELS      8
#define AND_PER_LEVEL 4096
#define NOT_PER_LEVEL 2048
#define LEVEL_N       (AND_PER_LEVEL + NOT_PER_LEVEL)
#define N_HIDDEN      1024
#define N_HID_LAYERS  8
#define LN_EPS        1e-5f

// ---------------------------------------------------------------------------
// Scratch: static device globals. Weights stored TRANSPOSED [N][K] row-major
// (k-contiguous) so B fragments load with plain non-trans ldmatrix.
// ---------------------------------------------------------------------------
__device__ __align__(256) __nv_bfloat16 g_winT_hi [(size_t)1024 * 512];
__device__ __align__(256) __nv_bfloat16 g_winT_lo [(size_t)1024 * 512];
__device__ __align__(256) __nv_bfloat16 g_whidT_hi[(size_t)8 * 1024 * 1024];
__device__ __align__(256) __nv_bfloat16 g_whidT_lo[(size_t)8 * 1024 * 1024];
__device__ __align__(256) __nv_bfloat16 g_woutT_hi[(size_t)256 * 1024];
__device__ __align__(256) __nv_bfloat16 g_woutT_lo[(size_t)256 * 1024];
__device__ __align__(256) __nv_bfloat16 g_act0_hi [(size_t)4096 * 1024];
__device__ __align__(256) __nv_bfloat16 g_act0_lo [(size_t)4096 * 1024];
__device__ __align__(256) __nv_bfloat16 g_act1_hi [(size_t)4096 * 1024];
__device__ __align__(256) __nv_bfloat16 g_act1_lo [(size_t)4096 * 1024];

// ---------------------------------------------------------------------------
__device__ __forceinline__ void split2(float v, __nv_bfloat16& hi, __nv_bfloat16& lo) {
    hi = __float2bfloat16(v);
    lo = __float2bfloat16(v - __bfloat162float(hi));
}

__device__ __forceinline__ uint32_t smem_u32(const void* p) {
    uint32_t a;
    asm("{ .reg .u64 t; cvta.to.shared.u64 t, %1; cvt.u32.u64 %0, t; }" : "=r"(a) : "l"(p));
    return a;
}

#define CP_ASYNC16(dst, src) \
    asm volatile("cp.async.cg.shared.global [%0], [%1], 16;" :: "r"(dst), "l"(src) : "memory")
#define CP_COMMIT() asm volatile("cp.async.commit_group;" ::: "memory")
#define CP_WAIT1()  asm volatile("cp.async.wait_group 1;" ::: "memory")
#define CP_WAIT0()  asm volatile("cp.async.wait_group 0;" ::: "memory")

__device__ __forceinline__ void ldsm4(uint32_t r[4], uint32_t addr) {
    asm volatile("ldmatrix.sync.aligned.m8n8.x4.shared.b16 {%0,%1,%2,%3}, [%4];"
                 : "=r"(r[0]), "=r"(r[1]), "=r"(r[2]), "=r"(r[3]) : "r"(addr));
}

__device__ __forceinline__ void mma_bf16(float c[4], const uint32_t a[4], const uint32_t b[2]) {
    asm volatile("mma.sync.aligned.m16n8k16.row.col.f32.bf16.bf16.f32 "
                 "{%0,%1,%2,%3}, {%4,%5,%6,%7}, {%8,%9}, {%0,%1,%2,%3};"
                 : "+f"(c[0]), "+f"(c[1]), "+f"(c[2]), "+f"(c[3])
                 : "r"(a[0]), "r"(a[1]), "r"(a[2]), "r"(a[3]), "r"(b[0]), "r"(b[1]));
}

// ---------------------------------------------------------------------------
// Elementwise kernels
// ---------------------------------------------------------------------------
// Transpose + split: src [R,C] f32 (layer z) -> dst [C][R] bf16 hi/lo.
// dst_sel: 0 -> W_in, 1 -> W_hid, 2 -> W_out
__global__ void tsplit_kernel(const float* __restrict__ src, int R, int C, int dst_sel) {
    __shared__ float t[32][33];
    const int layer = blockIdx.z;
    const float* sp = src + (size_t)layer * R * C;
    __nv_bfloat16 *hi, *lo;
    if (dst_sel == 0)      { hi = g_winT_hi;  lo = g_winT_lo; }
    else if (dst_sel == 1) { hi = g_whidT_hi + (size_t)layer * R * C;
                             lo = g_whidT_lo + (size_t)layer * R * C; }
    else                   { hi = g_woutT_hi; lo = g_woutT_lo; }
    const int c0 = blockIdx.x * 32, r0 = blockIdx.y * 32;
    const int tx = threadIdx.x, ty = threadIdx.y;
#pragma unroll
    for (int j = ty; j < 32; j += 8) t[j][tx] = sp[(size_t)(r0 + j) * C + c0 + tx];
    __syncthreads();
#pragma unroll
    for (int j = ty; j < 32; j += 8) {
        float v = t[tx][j];   // src[(r0+tx)*C + (c0+j)]
        __nv_bfloat16 h, l; split2(v, h, l);
        size_t o = (size_t)(c0 + j) * R + r0 + tx;   // dst[n][k]
        hi[o] = h; lo[o] = l;
    }
}

__global__ void init_kernel(const float* __restrict__ embd, float* __restrict__ out) {
    int i = blockIdx.x * blockDim.x + threadIdx.x;
    if (i < N_INPUTS * N_EMBD) out[i] = embd[i];
}

// Fused gather (h = [embd[xa], embd[ya]] -> act0, 4096x512 hi/lo) + NOT scatter.
#define GATHER_WORK (AND_PER_LEVEL * 512)
#define NOT_WORK    (NOT_PER_LEVEL * N_EMBD)
__global__ void gather_not_kernel(float* __restrict__ node,
                                  const int* __restrict__ xe, const int* __restrict__ ye,
                                  int s) {
    int i = blockIdx.x * blockDim.x + threadIdx.x;
    if (i < GATHER_WORK) {
        int m = i >> 9, c = i & 511;
        int src = (c < 256) ? xe[s + m] : ye[s + m];
        float v = node[(size_t)src * N_EMBD + (c & 255)];
        __nv_bfloat16 h, l; split2(v, h, l);
        g_act0_hi[i] = h; g_act0_lo[i] = l;
    } else if (i < GATHER_WORK + NOT_WORK) {
        int j = i - GATHER_WORK;
        int r = j >> 8, c = j & 255;
        int src = xe[s + AND_PER_LEVEL + r];
        node[(size_t)(s + AND_PER_LEVEL + r) * N_EMBD + c] = -node[(size_t)src * N_EMBD + c];
    }
}

// ---------------------------------------------------------------------------
// Split-bf16 GEMM via raw mma.sync.m16n8k16 + ldmatrix. 128 threads / 4 warps.
// C = (Ahi+Alo)@(Bhi+Blo) dropping lo*lo. Block tile BM x BN, K-chunk 32/stage.
// Warp tile 64 x 64: 4 m16-tiles x 8 n8-tiles. acc = 128 f32/lane.
// Per k16: hh (32 mma, D=32) -> lh (32) -> hl (32). Peak live regs ~215.
// 2-stage cp.async pipeline; 2 CTAs/SM.
// A: activations [M][K] row-major. B: transposed weights [N][K] row-major.
// fuse=1: relu(x+bias) -> bf16 hi/lo act[out_sel]. fuse=2: bias+LayerNorm -> outp.
// ---------------------------------------------------------------------------
#define LD40 40   // halves per smem row (80 B pitch: 16B-aligned, ldmatrix conflict-free)

template<int BM, int BN>
__global__ __launch_bounds__(128, 2) void gemm_mma(
    int K, int Nout, int a_sel, int b_sel, int layer, int out_sel, int fuse,
    const float* __restrict__ bias, float* __restrict__ outp, int s,
    const float* __restrict__ ln_g, const float* __restrict__ ln_b) {

    constexpr int WCOLS = BN / 64;          // 2 (hidden) or 4 (output)
    constexpr int WROWS = 4 / WCOLS;        // 2 or 1
    constexpr uint32_t ATILE = (uint32_t)BM * LD40 * 2u;   // bytes per A half-tile
    constexpr uint32_t BTILE = (uint32_t)BN * LD40 * 2u;
    constexpr uint32_t SS    = 2u * ATILE + 2u * BTILE;    // stage bytes

    extern __shared__ __align__(128) char dsm[];

    const int tid = threadIdx.x, warpId = tid >> 5, lane = tid & 31;
    const int wm = warpId / WCOLS, wn = warpId % WCOLS;
    const int rowBase = blockIdx.y * BM;
    const int colBase = blockIdx.x * BN;

    const __nv_bfloat16* Ahi = a_sel ? g_act1_hi : g_act0_hi;
    const __nv_bfloat16* Alo = a_sel ? g_act1_lo : g_act0_lo;
    const __nv_bfloat16 *Bhi, *Blo;
    if (b_sel == 0)      { Bhi = g_winT_hi;  Blo = g_winT_lo; }
    else if (b_sel == 1) { Bhi = g_whidT_hi + (size_t)layer * N_HIDDEN * N_HIDDEN;
                           Blo = g_whidT_lo + (size_t)layer * N_HIDDEN * N_HIDDEN; }
    else                 { Bhi = g_woutT_hi; Blo = g_woutT_lo; }

    const uint32_t sm0 = smem_u32(dsm);

    // ldmatrix per-lane selectors (PTX ISA fragment layouts)
    const uint32_t aRow = lane & 15;                   // rows of 16-row tile
    const uint32_t aCol = (lane >> 4) << 3;            // k 0 / 8
    const uint32_t bRow = ((lane >> 4) << 3) + (lane & 7);  // n within 16-group
    const uint32_t bCol = ((lane >> 3) & 1) << 3;      // k 0 / 8

    float acc[4][8][4];
#pragma unroll
    for (int m = 0; m < 4; m++)
#pragma unroll
        for (int t = 0; t < 8; t++)
#pragma unroll
            for (int j = 0; j < 4; j++) acc[m][t][j] = 0.0f;

    const int NK = K >> 5;   // 32-K stages

    auto load_stage = [&](int stg, int k0) {
        const uint32_t sb = sm0 + (uint32_t)stg * SS;
        // A hi/lo: BM x 32 halves = BM*4 16B vectors per half
#pragma unroll
        for (int h = 0; h < 2; h++) {
            const __nv_bfloat16* ap = h ? Alo : Ahi;
            const uint32_t so = sb + h * ATILE;
#pragma unroll
            for (int i = 0; i < (BM * 4) / 128; i++) {
                int v = tid + i * 128;
                int r = v >> 2, cv = v & 3;
                CP_ASYNC16(so + (uint32_t)(r * LD40 + cv * 8) * 2u,
                           ap + (size_t)(rowBase + r) * K + k0 + cv * 8);
            }
        }
        // B hi/lo: BN x 32 halves (BT rows = n, k-contiguous)
#pragma unroll
        for (int h = 0; h < 2; h++) {
            const __nv_bfloat16* bp = h ? Blo : Bhi;
            const uint32_t so = sb + 2u * ATILE + h * BTILE;
#pragma unroll
            for (int i = 0; i < (BN * 4) / 128; i++) {
                int v = tid + i * 128;
                int r = v >> 2, cv = v & 3;
                CP_ASYNC16(so + (uint32_t)(r * LD40 + cv * 8) * 2u,
                           bp + (size_t)(colBase + r) * K + k0 + cv * 8);
            }
        }
        CP_COMMIT();
    };

    load_stage(0, 0);
    load_stage(1, 32);

    for (int kt = 0; kt < NK; kt++) {
        if (kt + 1 < NK) CP_WAIT1(); else CP_WAIT0();
        __syncthreads();

        const uint32_t sb  = sm0 + (uint32_t)(kt & 1) * SS;
        const uint32_t aHi = sb, aLo = sb + ATILE;
        const uint32_t bHi = sb + 2u * ATILE, bLo = bHi + BTILE;

#pragma unroll
        for (int ks = 0; ks < 32; ks += 16) {
            const uint32_t aoff = ((wm * 64 + aRow) * LD40 + ks + aCol) * 2u;
            uint32_t ah[4][4];
#pragma unroll
            for (int m = 0; m < 4; m++)
                ldsm4(ah[m], aHi + aoff + (uint32_t)(m * 16 * LD40 * 2));
            uint32_t bh[4][4];
#pragma unroll
            for (int p = 0; p < 4; p++)
                ldsm4(bh[p], bHi + ((wn * 64 + p * 16 + bRow) * LD40 + ks + bCol) * 2u);
            // hi*hi (reuse distance 32)
#pragma unroll
            for (int m = 0; m < 4; m++)
#pragma unroll
                for (int t = 0; t < 8; t++)
                    mma_bf16(acc[m][t], ah[m], &bh[t >> 1][(t & 1) * 2]);
            // lo*hi
            {
                uint32_t al[4][4];
#pragma unroll
                for (int m = 0; m < 4; m++)
                    ldsm4(al[m], aLo + aoff + (uint32_t)(m * 16 * LD40 * 2));
#pragma unroll
                for (int m = 0; m < 4; m++)
#pragma unroll
                    for (int t = 0; t < 8; t++)
                        mma_bf16(acc[m][t], al[m], &bh[t >> 1][(t & 1) * 2]);
            }
            // hi*lo
            {
                uint32_t bl[4][4];
#pragma unroll
                for (int p = 0; p < 4; p++)
                    ldsm4(bl[p], bLo + ((wn * 64 + p * 16 + bRow) * LD40 + ks + bCol) * 2u);
#pragma unroll
                for (int m = 0; m < 4; m++)
#pragma unroll
                    for (int t = 0; t < 8; t++)
                        mma_bf16(acc[m][t], ah[m], &bl[t >> 1][(t & 1) * 2]);
            }
        }

        if (kt + 2 < NK) {
            __syncthreads();                 // stage fully consumed before overwrite
            load_stage(kt & 1, (kt + 2) * 32);
        }
    }
    __syncthreads();

    // acc layout: c0,c1 = row (lane>>2), cols (lane&3)*2,+1; c2,c3 = row+8.
    const int rl = lane >> 2, cl = (lane & 3) * 2;

    if (fuse == 1) {
        __nv_bfloat16* Ohi = out_sel ? g_act1_hi : g_act0_hi;
        __nv_bfloat16* Olo = out_sel ? g_act1_lo : g_act0_lo;
#pragma unroll
        for (int m = 0; m < 4; m++)
#pragma unroll
            for (int t = 0; t < 8; t++) {
                const float* c = acc[m][t];
                const int R = rowBase + wm * 64 + m * 16 + rl;
                const int C = colBase + wn * 64 + t * 8 + cl;
                float b0 = __ldg(bias + C), b1 = __ldg(bias + C + 1);
                float v0 = fmaxf(c[0] + b0, 0.0f), v1 = fmaxf(c[1] + b1, 0.0f);
                float v2 = fmaxf(c[2] + b0, 0.0f), v3 = fmaxf(c[3] + b1, 0.0f);
                __nv_bfloat16 h0, l0, h1, l1, h2, l2, h3, l3;
                split2(v0, h0, l0); split2(v1, h1, l1);
                split2(v2, h2, l2); split2(v3, h3, l3);
                size_t g0 = (size_t)R * Nout + C;
                size_t g1 = (size_t)(R + 8) * Nout + C;
                *(__nv_bfloat162*)(Ohi + g0) = __nv_bfloat162(h0, h1);
                *(__nv_bfloat162*)(Olo + g0) = __nv_bfloat162(l0, l1);
                *(__nv_bfloat162*)(Ohi + g1) = __nv_bfloat162(h2, h3);
                *(__nv_bfloat162*)(Olo + g1) = __nv_bfloat162(l2, l3);
            }
    } else {
        // fuse == 2: bias + LayerNorm. BM=64 (wm==0), BN=256, colBase==0.
        float2* s_red = (float2*)dsm;   // [64][WCOLS]
        float2 part[4][2];
#pragma unroll
        for (int m = 0; m < 4; m++) { part[m][0] = make_float2(0.f, 0.f);
                                      part[m][1] = make_float2(0.f, 0.f); }
#pragma unroll
        for (int m = 0; m < 4; m++)
#pragma unroll
            for (int t = 0; t < 8; t++) {
                float* c = acc[m][t];
                const int C = wn * 64 + t * 8 + cl;
                float b0 = __ldg(bias + C), b1 = __ldg(bias + C + 1);
                c[0] += b0; c[1] += b1; c[2] += b0; c[3] += b1;
                part[m][0].x += c[0] + c[1];
                part[m][0].y += c[0] * c[0] + c[1] * c[1];
                part[m][1].x += c[2] + c[3];
                part[m][1].y += c[2] * c[2] + c[3] * c[3];
            }
        // reduce over quad (lanes sharing a row)
#pragma unroll
        for (int m = 0; m < 4; m++)
#pragma unroll
            for (int h = 0; h < 2; h++) {
#pragma unroll
                for (int o = 1; o <= 2; o <<= 1) {
                    part[m][h].x += __shfl_xor_sync(0xFFFFFFFFu, part[m][h].x, o);
                    part[m][h].y += __shfl_xor_sync(0xFFFFFFFFu, part[m][h].y, o);
                }
                if ((lane & 3) == 0)
                    s_red[(m * 16 + h * 8 + rl) * WCOLS + wn] = part[m][h];
            }
        __syncthreads();
#pragma unroll
        for (int m = 0; m < 4; m++)
#pragma unroll
            for (int h = 0; h < 2; h++) {
                const int r = m * 16 + h * 8 + rl;
                float sum = 0.f, sq = 0.f;
#pragma unroll
                for (int w = 0; w < WCOLS; w++) {
                    float2 p = s_red[r * WCOLS + w];
                    sum += p.x; sq += p.y;
                }
                float mu  = sum * (1.0f / N_EMBD);
                float var = sq * (1.0f / N_EMBD) - mu * mu;
                float inv = rsqrtf(var + LN_EPS);
                float* orow = outp + (size_t)(s + rowBase + r) * N_EMBD;
#pragma unroll
                for (int t = 0; t < 8; t++) {
                    const int C = wn * 64 + t * 8 + cl;
                    float g0 = __ldg(ln_g + C), g1 = __ldg(ln_g + C + 1);
                    float bb0 = __ldg(ln_b + C), bb1 = __ldg(ln_b + C + 1);
                    float v0 = (acc[m][t][h * 2 + 0] - mu) * inv * g0 + bb0;
                    float v1 = (acc[m][t][h * 2 + 1] - mu) * inv * g1 + bb1;
                    *(float2*)(orow + C) = make_float2(v0, v1);
                }
            }
    }
}

// ---------------------------------------------------------------------------
// Launch: kernel launches only; graph-capturable; no allocation; no sync.
// First GEMM at launch index 3 (ncu capture slot).
// ---------------------------------------------------------------------------
extern "C" void kernel_launch(void* const* d_in, const int* in_sizes, int n_in,
                              void* d_out, int out_size) {
    (void)in_sizes; (void)n_in; (void)out_size;

    const int*   xe         = (const int*)d_in[1];
    const int*   ye         = (const int*)d_in[2];
    const float* input_embd = (const float*)d_in[3];
    const float* W_in       = (const float*)d_in[4];
    const float* b_in       = (const float*)d_in[5];
    const float* W_hid      = (const float*)d_in[6];
    const float* b_hid      = (const float*)d_in[7];
    const float* W_out      = (const float*)d_in[8];
    const float* b_out      = (const float*)d_in[9];
    const float* ln_g       = (const float*)d_in[10];
    const float* ln_b       = (const float*)d_in[11];
    float*       out        = (float*)d_out;

    // Stage sizes (bytes): 2*(A hi+lo) + 2*(B hi+lo), LD40 pitch
    const uint32_t SS_H = 2u * (128 * LD40 * 2) + 2u * (128 * LD40 * 2);  // 40960
    const uint32_t SS_O = 2u * (64 * LD40 * 2) + 2u * (256 * LD40 * 2);   // 51200
    cudaFuncSetAttribute((const void*)gemm_mma<128, 128>,
                         cudaFuncAttributeMaxDynamicSharedMemorySize, 2 * SS_H);
    cudaFuncSetAttribute((const void*)gemm_mma<64, 256>,
                         cudaFuncAttributeMaxDynamicSharedMemorySize, 2 * SS_O);

    const dim3 gridH(N_HIDDEN / 128, AND_PER_LEVEL / 128);  // (8, 32) = 256 CTAs
    const dim3 gridO(1, AND_PER_LEVEL / 64);                // (1, 64) = 64 CTAs
    const int  gnBlocks = (GATHER_WORK + NOT_WORK + 255) / 256;
    const dim3 tb(32, 8);

    // --- prologue arranged so launch #3 is a GEMM (ncu capture target) ---
    tsplit_kernel<<<dim3(1024 / 32, 512 / 32, 1), tb>>>(W_in, 512, 1024, 0);      // 0
    init_kernel<<<(N_INPUTS * N_EMBD + 255) / 256, 256>>>(input_embd, out);       // 1
    gather_not_kernel<<<gnBlocks, 256>>>(out, xe, ye, N_INPUTS);                  // 2
    gemm_mma<128, 128><<<gridH, 128, 2 * SS_H>>>(512, N_HIDDEN, 0, 0, 0, 1, 1,
                                                 b_in, nullptr, 0, nullptr, nullptr); // 3
    tsplit_kernel<<<dim3(1024 / 32, 1024 / 32, 8), tb>>>(W_hid, 1024, 1024, 1);   // 4
    tsplit_kernel<<<dim3(256 / 32, 1024 / 32, 1), tb>>>(W_out, 1024, 256, 2);     // 5

    for (int l = 0; l < N_LEVELS; l++) {
        const int s = N_INPUTS + l * LEVEL_N;

        if (l > 0) {
            gather_not_kernel<<<gnBlocks, 256>>>(out, xe, ye, s);
            gemm_mma<128, 128><<<gridH, 128, 2 * SS_H>>>(512, N_HIDDEN, 0, 0, 0, 1, 1,
                                                         b_in, nullptr, 0, nullptr, nullptr);
        }

        for (int i = 0; i < N_HID_LAYERS; i++) {
            int a_sel = (i & 1) ? 0 : 1;
            int o_sel = 1 - a_sel;
            gemm_mma<128, 128><<<gridH, 128, 2 * SS_H>>>(N_HIDDEN, N_HIDDEN, a_sel, 1, i, o_sel, 1,
                                                         b_hid + (size_t)i * N_HIDDEN,
                                                         nullptr, 0, nullptr, nullptr);
        }

        gemm_mma<64, 256><<<gridO, 128, 2 * SS_O>>>(N_HIDDEN, N_EMBD, 1, 2, 0, 0, 2,
                                                    b_out, out, s, ln_g, ln_b);
    }
}